// round 2
// baseline (speedup 1.0000x reference)
#include <cuda_runtime.h>

// B=8, T=4096, D=2048, W=4
// y[b,t,d] = silu( sum_{k=0..3} w[k,d] * x[b, t-3+k, d] )  (zero-pad t<0)

#define B_DIM 8
#define T_DIM 4096
#define D_DIM 2048
#define D4    (D_DIM / 4)       // 512 float4 per row
#define TC    16                // t-values per thread (sliding window)
#define NCH   (T_DIM / TC)      // 256 chunks per batch

// silu(v) = v * sigmoid(v) = 0.5*v*(1 + tanh(0.5*v))  -> single MUFU.TANH
__device__ __forceinline__ float silu_f(float v) {
    float t;
    asm("tanh.approx.f32 %0, %1;" : "=f"(t) : "f"(0.5f * v));
    return fmaf(0.5f * v, t, 0.5f * v);
}

__global__ __launch_bounds__(256) void conv_silu_kernel(
    const float4* __restrict__ x,     // [B, T, D4]
    const float4* __restrict__ w,     // [4, D4]
    float4* __restrict__ y)           // [B, T, D4]
{
    unsigned idx = blockIdx.x * blockDim.x + threadIdx.x;
    // idx -> (b, tc, d4), d4 fastest for coalescing
    unsigned d4   = idx & (D4 - 1);
    unsigned rest = idx >> 9;             // / D4
    unsigned tc   = rest & (NCH - 1);
    unsigned b    = rest >> 8;            // / NCH

    size_t base = ((size_t)b * T_DIM + (size_t)tc * TC) * D4 + d4;
    const float4* __restrict__ xp = x + base;
    float4*       __restrict__ yp = y + base;

    // per-channel weights (tiny array; L2-resident)
    float4 w0 = w[0 * D4 + d4];
    float4 w1 = w[1 * D4 + d4];
    float4 w2 = w[2 * D4 + d4];
    float4 w3 = w[3 * D4 + d4];

    // history: x[t-3], x[t-2], x[t-1]
    float4 xm3, xm2, xm1;
    if (tc > 0) {
        xm3 = xp[-3 * (int)D4];
        xm2 = xp[-2 * (int)D4];
        xm1 = xp[-1 * (int)D4];
    } else {
        xm3 = make_float4(0.f, 0.f, 0.f, 0.f);
        xm2 = xm3;
        xm1 = xm3;
    }

#pragma unroll
    for (int i = 0; i < TC; ++i) {
        float4 cur = xp[i * D4];

        float4 acc;
        acc.x = fmaf(w3.x, cur.x, fmaf(w2.x, xm1.x, fmaf(w1.x, xm2.x, w0.x * xm3.x)));
        acc.y = fmaf(w3.y, cur.y, fmaf(w2.y, xm1.y, fmaf(w1.y, xm2.y, w0.y * xm3.y)));
        acc.z = fmaf(w3.z, cur.z, fmaf(w2.z, xm1.z, fmaf(w1.z, xm2.z, w0.z * xm3.z)));
        acc.w = fmaf(w3.w, cur.w, fmaf(w2.w, xm1.w, fmaf(w1.w, xm2.w, w0.w * xm3.w)));

        float4 out;
        out.x = silu_f(acc.x);
        out.y = silu_f(acc.y);
        out.z = silu_f(acc.z);
        out.w = silu_f(acc.w);

        yp[i * D4] = out;

        xm3 = xm2;
        xm2 = xm1;
        xm1 = cur;
    }
}

extern "C" void kernel_launch(void* const* d_in, const int* in_sizes, int n_in,
                              void* d_out, int out_size)
{
    const float4* x = (const float4*)d_in[0];   // (B, T, D) float32
    const float4* w = (const float4*)d_in[1];   // (W, 1, D) float32
    float4* y = (float4*)d_out;

    const unsigned total_threads = B_DIM * NCH * D4;   // 1,048,576
    const unsigned block = 256;
    const unsigned grid = total_threads / block;       // 4096

    conv_silu_kernel<<<grid, block>>>(x, w, y);
}

// round 3
// speedup vs baseline: 1.0229x; 1.0229x over previous
#include <cuda_runtime.h>

// B=8, T=4096, D=2048, W=4
// y[b,t,d] = silu( sum_{k=0..3} w[k,d] * x[b, t-3+k, d] )  (zero-pad t<0)

#define B_DIM 8
#define T_DIM 4096
#define D_DIM 2048
#define D4    (D_DIM / 4)       // 512 float4 per row
#define TC    8                 // t-values per thread (sliding window)
#define NCH   (T_DIM / TC)      // 512 chunks per batch

// silu(v) = 0.5*v*(1 + tanh(0.5*v))  -> single MUFU.TANH
__device__ __forceinline__ float silu_f(float v) {
    float t;
    asm("tanh.approx.f32 %0, %1;" : "=f"(t) : "f"(0.5f * v));
    return fmaf(0.5f * v, t, 0.5f * v);
}

__global__ __launch_bounds__(256) void conv_silu_kernel(
    const float4* __restrict__ x,     // [B, T, D4]
    const float4* __restrict__ w,     // [4, D4]
    float4* __restrict__ y)           // [B, T, D4]
{
    unsigned idx = blockIdx.x * blockDim.x + threadIdx.x;
    // idx -> (b, tc, d4), d4 fastest for coalescing
    unsigned d4   = idx & (D4 - 1);
    unsigned rest = idx >> 9;             // / D4
    unsigned tc   = rest & (NCH - 1);
    unsigned b    = rest >> 9;            // / NCH

    size_t base = ((size_t)b * T_DIM + (size_t)tc * TC) * D4 + d4;
    const float4* __restrict__ xp = x + base;
    float4*       __restrict__ yp = y + base;

    // per-channel weights (tiny; L2-resident)
    float4 w0 = w[0 * D4 + d4];
    float4 w1 = w[1 * D4 + d4];
    float4 w2 = w[2 * D4 + d4];
    float4 w3 = w[3 * D4 + d4];

    // history: x[t-3], x[t-2], x[t-1]
    float4 xm3, xm2, xm1;
    if (tc > 0) {
        xm3 = xp[-3 * (int)D4];
        xm2 = xp[-2 * (int)D4];
        xm1 = xp[-1 * (int)D4];
    } else {
        xm3 = make_float4(0.f, 0.f, 0.f, 0.f);
        xm2 = xm3;
        xm1 = xm3;
    }

#pragma unroll
    for (int i = 0; i < TC; ++i) {
        float4 cur = xp[i * D4];

        float4 acc;
        acc.x = fmaf(w3.x, cur.x, fmaf(w2.x, xm1.x, fmaf(w1.x, xm2.x, w0.x * xm3.x)));
        acc.y = fmaf(w3.y, cur.y, fmaf(w2.y, xm1.y, fmaf(w1.y, xm2.y, w0.y * xm3.y)));
        acc.z = fmaf(w3.z, cur.z, fmaf(w2.z, xm1.z, fmaf(w1.z, xm2.z, w0.z * xm3.z)));
        acc.w = fmaf(w3.w, cur.w, fmaf(w2.w, xm1.w, fmaf(w1.w, xm2.w, w0.w * xm3.w)));

        float4 out;
        out.x = silu_f(acc.x);
        out.y = silu_f(acc.y);
        out.z = silu_f(acc.z);
        out.w = silu_f(acc.w);

        // streaming store: evict-first in L2 (output is never re-read)
        __stcs(&yp[i * D4], out);

        xm3 = xm2;
        xm2 = xm1;
        xm1 = cur;
    }
}

extern "C" void kernel_launch(void* const* d_in, const int* in_sizes, int n_in,
                              void* d_out, int out_size)
{
    const float4* x = (const float4*)d_in[0];   // (B, T, D) float32
    const float4* w = (const float4*)d_in[1];   // (W, 1, D) float32
    float4* y = (float4*)d_out;

    const unsigned total_threads = B_DIM * NCH * D4;   // 2,097,152
    const unsigned block = 256;
    const unsigned grid = total_threads / block;       // 8192

    conv_silu_kernel<<<grid, block>>>(x, w, y);
}